// round 14
// baseline (speedup 1.0000x reference)
#include <cuda_runtime.h>
#include <cuda_bf16.h>
#include <cstdint>

// 3D LUT trilinear (color grade), lut (3,33,33,33) f32, x (4,3,1080,1920) f32.
//
// Round-14: single-variable experiment on the R13 champion — THREADS 1024->768.
// Evidence: 62 regs x 1024 thr = 63.5K of 64K RF (file full); instruction cuts
// stopped moving wall time; both regression rounds lost via register pressure.
// 768 threads raises the per-thread budget to 85 regs so ptxas can schedule
// deeper (batched LDS, live prefetch, cross-pixel ILP), at the cost of 24 vs
// 32 warps of latency hiding.
// Body identical to R13: fused magic floor (FFMA_rz) feeding index IMADs,
// prepacked u32 LUT in 143.7KB smem (c1 12b @0-11, c0 11b @12-22 mantissa-
// aligned, c2 8b @24-31 via PRMT), 8x LDS.32/px random gather, prefetched
// __ldcs/__stcs float4 streams, grid = SM count.

#define LUT_DIM   33
#define LUT_N     (LUT_DIM * LUT_DIM * LUT_DIM)   // 35937
#define LUT_NPAD  35940
#define IMG_HW    (1080 * 1920)                   // 2073600
#define N_IMG     4
#define THREADS   768

#define SMEM_BYTES (LUT_NPAD * 4)                 // 143760

__device__ uint32_t g_packed[LUT_NPAD];

__global__ void pack_lut_kernel(const float* __restrict__ lut) {
    int i = blockIdx.x * blockDim.x + threadIdx.x;
    if (i >= LUT_N) return;
    float c0 = lut[i];
    float c1 = lut[LUT_N + i];
    float c2 = lut[2 * LUT_N + i];
    uint32_t u0 = (uint32_t)(fminf(fmaxf(c0, 0.f), 1.f) * 2047.f + 0.5f);
    uint32_t u1 = (uint32_t)(fminf(fmaxf(c1, 0.f), 1.f) * 4095.f + 0.5f);
    uint32_t u2 = (uint32_t)(fminf(fmaxf(c2, 0.f), 1.f) * 255.f + 0.5f);
    g_packed[i] = u1 | (u0 << 12) | (u2 << 24);
}

// c0: 11 bits @ 12-22 (mantissa-aligned): 1 LOP3
__device__ __forceinline__ float dec0(uint32_t e) {
    return __uint_as_float((e & 0x007FF000u) | 0x3F800000u);
}
// c1: 12 bits @ 0-11 -> mantissa 11-22: shift + LOP3
__device__ __forceinline__ float dec1(uint32_t e) {
    return __uint_as_float(((e << 11) & 0x007FF800u) | 0x3F800000u);
}
// c2: 8 bits @ 24-31 -> mantissa bits 8-15 via single PRMT: 1 + u2*2^-15
__device__ __forceinline__ float dec2(uint32_t e) {
    return __uint_as_float(__byte_perm(e, 0x3F800000u, 0x7634));
}

__device__ __forceinline__ void process_pixel(
    const uint32_t* __restrict__ sLut,
    float r, float g, float b, float& o0, float& o1, float& o2)
{
    const float INV   = (float)(32.0 / 1.000001);
    const float MAGIC = 8388608.0f;               // 2^23

    // fused magic floor: one FFMA_rz per channel; raw bits feed index IMADs.
    float sr = __fmaf_rz(r, INV, MAGIC);
    float sg = __fmaf_rz(g, INV, MAGIC);
    float sb = __fmaf_rz(b, INV, MAGIC);
    uint32_t rraw = __float_as_uint(sr);          // 0x4B000000 + ri
    uint32_t graw = __float_as_uint(sg);
    uint32_t braw = __float_as_uint(sb);
    const uint32_t CRAW = 1123u * 0x4B000000u;    // fold of the 3 biases
    uint32_t base = (braw * LUT_DIM + graw) * LUT_DIM + rraw - CRAW;

    // all 8 corner loads first (latency overlaps the weight tree below)
    uint32_t e00a = sLut[base];
    uint32_t e00b = sLut[base + 1];
    uint32_t e01a = sLut[base + LUT_DIM];
    uint32_t e01b = sLut[base + LUT_DIM + 1];
    uint32_t e10a = sLut[base + LUT_DIM * LUT_DIM];
    uint32_t e10b = sLut[base + LUT_DIM * LUT_DIM + 1];
    uint32_t e11a = sLut[base + LUT_DIM * LUT_DIM + LUT_DIM];
    uint32_t e11b = sLut[base + LUT_DIM * LUT_DIM + LUT_DIM + 1];

    float flr = sr - MAGIC;
    float flg = sg - MAGIC;
    float flb = sb - MAGIC;
    float fr = fmaf(r, INV, -flr);
    float fg = fmaf(g, INV, -flg);
    float fb = fmaf(b, INV, -flb);

    // (db,dg) weights, complements via FFMA folds
    float wbg10 = fmaf(fg, -fb, fb);              // fb*(1-fg)
    float wbg11 = fb * fg;
    float wb0   = fmaf(fb, -1.f, 1.f);            // 1-fb
    float wbg01 = wb0 * fg;
    float wbg00 = fmaf(fg, -wb0, wb0);            // (1-fb)*(1-fg)

    float a0, a1, a2;
    {
        float w1 = wbg00 * fr;
        float w0 = fmaf(fr, -wbg00, wbg00);
        a0 = w0 * dec0(e00a); a1 = w0 * dec1(e00a); a2 = w0 * dec2(e00a);
        a0 = fmaf(w1, dec0(e00b), a0); a1 = fmaf(w1, dec1(e00b), a1); a2 = fmaf(w1, dec2(e00b), a2);
    }
    {
        float w1 = wbg01 * fr;
        float w0 = fmaf(fr, -wbg01, wbg01);
        a0 = fmaf(w0, dec0(e01a), a0); a1 = fmaf(w0, dec1(e01a), a1); a2 = fmaf(w0, dec2(e01a), a2);
        a0 = fmaf(w1, dec0(e01b), a0); a1 = fmaf(w1, dec1(e01b), a1); a2 = fmaf(w1, dec2(e01b), a2);
    }
    {
        float w1 = wbg10 * fr;
        float w0 = fmaf(fr, -wbg10, wbg10);
        a0 = fmaf(w0, dec0(e10a), a0); a1 = fmaf(w0, dec1(e10a), a1); a2 = fmaf(w0, dec2(e10a), a2);
        a0 = fmaf(w1, dec0(e10b), a0); a1 = fmaf(w1, dec1(e10b), a1); a2 = fmaf(w1, dec2(e10b), a2);
    }
    {
        float w1 = wbg11 * fr;
        float w0 = fmaf(fr, -wbg11, wbg11);
        a0 = fmaf(w0, dec0(e11a), a0); a1 = fmaf(w0, dec1(e11a), a1); a2 = fmaf(w0, dec2(e11a), a2);
        a0 = fmaf(w1, dec0(e11b), a0); a1 = fmaf(w1, dec1(e11b), a1); a2 = fmaf(w1, dec2(e11b), a2);
    }

    const float S0 = 2048.0f / 2047.0f;           // 11-bit @ 2^-11
    const float S1 = 4096.0f / 4095.0f;           // 12-bit @ 2^-12
    const float S2 = 32768.0f / 255.0f;           // 8-bit  @ 2^-15
    o0 = fmaf(a0, S0, -S0);
    o1 = fmaf(a1, S1, -S1);
    o2 = fmaf(a2, S2, -S2);
}

__global__ void __launch_bounds__(THREADS, 1)
lut_apply_smem(const float* __restrict__ x, float* __restrict__ out, int stride)
{
    extern __shared__ uint32_t sLut[];

    // coalesced uint4 copy of the pre-packed table
    {
        const uint4* src = (const uint4*)g_packed;
        uint4* dst = (uint4*)sLut;
        for (int i = threadIdx.x; i < LUT_NPAD / 4; i += THREADS)
            dst[i] = src[i];
    }
    __syncthreads();

    const int quadsPerImg = IMG_HW / 4;                 // 518400
    const int quadsTotal  = N_IMG * quadsPerImg;        // 2073600
    const int STEP        = stride * 4;                 // pixels; < IMG_HW

    int t0 = blockIdx.x * THREADS + threadIdx.x;
    if (t0 >= quadsTotal) return;
    int n = t0 / quadsPerImg;
    int q = (t0 - n * quadsPerImg) * 4;
    size_t off = (size_t)n * 3 * IMG_HW;
    int iters = (quadsTotal - t0 + stride - 1) / stride;

    float4 r4 = __ldcs((const float4*)(x + off + q));
    float4 g4 = __ldcs((const float4*)(x + off + IMG_HW + q));
    float4 b4 = __ldcs((const float4*)(x + off + 2 * IMG_HW + q));

    int i = 0;
    while (true) {
        int nq = q + STEP;
        size_t noff = off;
        if (nq >= IMG_HW) { nq -= IMG_HW; noff += 3 * (size_t)IMG_HW; }
        float4 nr, ng, nb;
        bool have_next = (i + 1 < iters);
        if (have_next) {
            nr = __ldcs((const float4*)(x + noff + nq));
            ng = __ldcs((const float4*)(x + noff + IMG_HW + nq));
            nb = __ldcs((const float4*)(x + noff + 2 * IMG_HW + nq));
        }

        float4 o0, o1, o2;
        process_pixel(sLut, r4.x, g4.x, b4.x, o0.x, o1.x, o2.x);
        process_pixel(sLut, r4.y, g4.y, b4.y, o0.y, o1.y, o2.y);
        process_pixel(sLut, r4.z, g4.z, b4.z, o0.z, o1.z, o2.z);
        process_pixel(sLut, r4.w, g4.w, b4.w, o0.w, o1.w, o2.w);

        __stcs((float4*)(out + off + q), o0);
        __stcs((float4*)(out + off + IMG_HW + q), o1);
        __stcs((float4*)(out + off + 2 * IMG_HW + q), o2);

        if (!have_next) break;
        i++; q = nq; off = noff;
        r4 = nr; g4 = ng; b4 = nb;
    }
}

extern "C" void kernel_launch(void* const* d_in, const int* in_sizes, int n_in,
                              void* d_out, int out_size) {
    const float* lut = (const float*)d_in[0];
    const float* x   = (const float*)d_in[1];
    float* out = (float*)d_out;

    static int ctas = 0;
    if (ctas == 0) {
        cudaDeviceGetAttribute(&ctas, cudaDevAttrMultiProcessorCount, 0);
        if (ctas <= 0) ctas = 148;
        cudaFuncSetAttribute(lut_apply_smem,
                             cudaFuncAttributeMaxDynamicSharedMemorySize,
                             SMEM_BYTES);
    }

    pack_lut_kernel<<<(LUT_N + 255) / 256, 256>>>(lut);
    lut_apply_smem<<<ctas, THREADS, SMEM_BYTES>>>(x, out, ctas * THREADS);
}